// round 1
// baseline (speedup 1.0000x reference)
#include <cuda_runtime.h>
#include <math.h>

#define E_  8
#define H_  2048
#define I_  1024
#define I2_ 2048
#define K_  2
#define L_  4
#define R_  16
#define T_  4096
#define P_  (T_*K_)          // 8192 (token, slot) pairs

#define KT1  (H_ + L_*R_)    // 2112 extended K for gate_up GEMM
#define NKT1 (KT1/16)        // 132 k-tiles
#define KT2  (I_ + L_*R_)    // 1088 extended K for down GEMM
#define NKT2 (KT2/16)        // 68 k-tiles

// -------- scratch (device globals; allocation-free) --------
__device__ float g_A1[(size_t)P_ * KT1];  // [s][2112]: gathered x + masked U
__device__ float g_A2[(size_t)P_ * KT2];  // [s][1088]: act + masked V
__device__ float g_D [(size_t)P_ * H_];   // [s][2048]: down output per pair
__device__ int   g_list[P_];              // sorted position -> pair id
__device__ int   g_pos [P_];              // pair id -> sorted position
__device__ int   g_off [E_ + 1];          // per-expert offsets

// ============================================================
// 1) Routing: group pairs by expert (single block).
// ============================================================
__global__ void k_route(const int* __restrict__ topk_ids) {
    __shared__ int cnt[E_];
    __shared__ int cur[E_];
    int tid = threadIdx.x;
    if (tid < E_) cnt[tid] = 0;
    __syncthreads();
    for (int p = tid; p < P_; p += blockDim.x)
        atomicAdd(&cnt[topk_ids[p]], 1);
    __syncthreads();
    if (tid == 0) {
        int acc = 0;
        for (int e = 0; e < E_; e++) { g_off[e] = acc; cur[e] = acc; acc += cnt[e]; }
        g_off[E_] = acc;
    }
    __syncthreads();
    for (int p = tid; p < P_; p += blockDim.x) {
        int e = topk_ids[p];
        int pos = atomicAdd(&cur[e], 1);
        g_list[pos] = p;
        g_pos[p]    = pos;
    }
}

// ============================================================
// 2) prep1: A1[s] = [ x[t] | one_hot(l) x U[p, :] ]
//    U[p,r] = dot(x[t], gu_a[l,e,r,:])
// ============================================================
__global__ __launch_bounds__(256) void k_prep1(
    const float* __restrict__ x, const float* __restrict__ gu_a,
    const int* __restrict__ topk_ids, const int* __restrict__ lora_idx) {
    int s = blockIdx.x;
    int p = g_list[s];
    int t = p >> 1;
    int e = topk_ids[p];
    int l = lora_idx[t];
    int tid = threadIdx.x;

    float* row = g_A1 + (size_t)s * KT1;
    const float4* x4 = (const float4*)(x + (size_t)t * H_);
    float4* r4 = (float4*)row;
    r4[tid]       = x4[tid];          // H_/4 = 512 float4, 2 per thread
    r4[tid + 256] = x4[tid + 256];
    if (tid < L_*R_) row[H_ + tid] = 0.f;
    __syncthreads();

    int lane = tid & 31, w = tid >> 5;   // 8 warps; warp w -> r = w, w+8
    const float4* a4 = (const float4*)(gu_a + (((size_t)l*E_ + e)*R_ + w) * H_);
    const float4* b4 = a4 + (size_t)8 * (H_/4);
    float sa = 0.f, sb = 0.f;
    for (int it = lane; it < H_/4; it += 32) {
        float4 xv = x4[it];
        float4 av = a4[it];
        float4 bv = b4[it];
        sa += xv.x*av.x + xv.y*av.y + xv.z*av.z + xv.w*av.w;
        sb += xv.x*bv.x + xv.y*bv.y + xv.z*bv.z + xv.w*bv.w;
    }
    #pragma unroll
    for (int off = 16; off; off >>= 1) {
        sa += __shfl_down_sync(0xffffffffu, sa, off);
        sb += __shfl_down_sync(0xffffffffu, sb, off);
    }
    if (lane == 0) {
        row[H_ + l*R_ + w]     = sa;
        row[H_ + l*R_ + w + 8] = sb;
    }
}

// ============================================================
// 3) GEMM1: for expert e, tile 128 pairs x (64 gate cols + 64 up cols),
//    K = 2112 (w13 rows ++ gu_b rows). SwiGLU fused -> writes act to A2.
// ============================================================
__global__ __launch_bounds__(256, 2) void k_gemm1(
    const float* __restrict__ w13, const float* __restrict__ gu_b) {
    int e   = blockIdx.z;
    int off = g_off[e];
    int cnt = g_off[e+1] - off;
    int m0  = blockIdx.y * 128;
    if (m0 >= cnt) return;
    int c0  = blockIdx.x * 64;

    __shared__ float As[2][16][128];
    __shared__ float Bs[2][16][128];

    int tid  = threadIdx.x;
    int tx   = tid & 15, ty = tid >> 4;
    int lrow = tid >> 1;
    int lcol = (tid & 1) * 8;

    int rA = m0 + lrow; if (rA > cnt - 1) rA = cnt - 1;
    const float* pA = g_A1 + (size_t)(off + rA) * KT1 + lcol;
    int colB = (lrow < 64) ? (c0 + lrow) : (I_ + c0 + lrow - 64);
    const float* pBmain = w13 + ((size_t)e * I2_ + colB) * H_ + lcol;

    float acc[8][8];
    #pragma unroll
    for (int i = 0; i < 8; i++)
        #pragma unroll
        for (int j = 0; j < 8; j++) acc[i][j] = 0.f;

    float4 va0, va1, vb0, vb1;
    { const float4* a = (const float4*)pA;     va0 = a[0]; va1 = a[1];
      const float4* b = (const float4*)pBmain; vb0 = b[0]; vb1 = b[1]; }

    for (int kt = 0; kt < NKT1; kt++) {
        int buf = kt & 1;
        {   float av[8] = {va0.x,va0.y,va0.z,va0.w,va1.x,va1.y,va1.z,va1.w};
            float bv[8] = {vb0.x,vb0.y,vb0.z,vb0.w,vb1.x,vb1.y,vb1.z,vb1.w};
            #pragma unroll
            for (int u = 0; u < 8; u++) {
                As[buf][lcol+u][lrow] = av[u];
                Bs[buf][lcol+u][lrow] = bv[u];
            }
        }
        __syncthreads();
        if (kt + 1 < NKT1) {
            int k2 = kt + 1;
            const float4* a = (const float4*)(pA + (size_t)k2 * 16);
            va0 = a[0]; va1 = a[1];
            const float* pb;
            if (k2 < H_/16) pb = pBmain + (size_t)k2 * 16;
            else pb = gu_b + (((size_t)(k2 - H_/16) * E_ + e) * I2_ + colB) * R_ + lcol;
            const float4* b = (const float4*)pb;
            vb0 = b[0]; vb1 = b[1];
        }
        #pragma unroll
        for (int k = 0; k < 16; k++) {
            float4 a0 = *(const float4*)&As[buf][k][ty*4];
            float4 a1 = *(const float4*)&As[buf][k][64 + ty*4];
            float4 b0 = *(const float4*)&Bs[buf][k][tx*4];
            float4 b1 = *(const float4*)&Bs[buf][k][64 + tx*4];
            float av[8] = {a0.x,a0.y,a0.z,a0.w,a1.x,a1.y,a1.z,a1.w};
            float bv[8] = {b0.x,b0.y,b0.z,b0.w,b1.x,b1.y,b1.z,b1.w};
            #pragma unroll
            for (int i = 0; i < 8; i++)
                #pragma unroll
                for (int j = 0; j < 8; j++)
                    acc[i][j] += av[i] * bv[j];
        }
        __syncthreads();
    }

    // epilogue: SwiGLU and write act into A2 (cols c0 + tx*4 .. +3)
    #pragma unroll
    for (int i = 0; i < 8; i++) {
        int m = (i < 4) ? (ty*4 + i) : (64 + ty*4 + i - 4);
        if (m0 + m >= cnt) continue;
        size_t s = (size_t)(off + m0 + m);
        float g0 = acc[i][0], g1 = acc[i][1], g2 = acc[i][2], g3 = acc[i][3];
        float4 o;
        o.x = acc[i][4] * (g0 / (1.f + expf(-g0)));
        o.y = acc[i][5] * (g1 / (1.f + expf(-g1)));
        o.z = acc[i][6] * (g2 / (1.f + expf(-g2)));
        o.w = acc[i][7] * (g3 / (1.f + expf(-g3)));
        *(float4*)(g_A2 + s * KT2 + c0 + tx*4) = o;
    }
}

// ============================================================
// 4) prep2: V[p,r] = dot(act[s], down_lora_a[l,e,r,:]) -> A2 tail
// ============================================================
__global__ __launch_bounds__(256) void k_prep2(
    const float* __restrict__ d_a,
    const int* __restrict__ topk_ids, const int* __restrict__ lora_idx) {
    int s = blockIdx.x;
    int p = g_list[s];
    int t = p >> 1;
    int e = topk_ids[p];
    int l = lora_idx[t];
    int tid = threadIdx.x;

    float* row = g_A2 + (size_t)s * KT2;
    if (tid < L_*R_) row[I_ + tid] = 0.f;
    __syncthreads();

    const float4* act4 = (const float4*)row;
    int lane = tid & 31, w = tid >> 5;
    const float4* a4 = (const float4*)(d_a + (((size_t)l*E_ + e)*R_ + w) * I_);
    const float4* b4 = a4 + (size_t)8 * (I_/4);
    float sa = 0.f, sb = 0.f;
    for (int it = lane; it < I_/4; it += 32) {
        float4 xv = act4[it];
        float4 av = a4[it];
        float4 bv = b4[it];
        sa += xv.x*av.x + xv.y*av.y + xv.z*av.z + xv.w*av.w;
        sb += xv.x*bv.x + xv.y*bv.y + xv.z*bv.z + xv.w*bv.w;
    }
    #pragma unroll
    for (int off = 16; off; off >>= 1) {
        sa += __shfl_down_sync(0xffffffffu, sa, off);
        sb += __shfl_down_sync(0xffffffffu, sb, off);
    }
    if (lane == 0) {
        row[I_ + l*R_ + w]     = sa;
        row[I_ + l*R_ + w + 8] = sb;
    }
}

// ============================================================
// 5) GEMM2: 128 pairs x 128 H-cols, K = 1088 (w2 ++ down_lora_b). -> g_D
// ============================================================
__global__ __launch_bounds__(256, 2) void k_gemm2(
    const float* __restrict__ w2, const float* __restrict__ d_b) {
    int e   = blockIdx.z;
    int off = g_off[e];
    int cnt = g_off[e+1] - off;
    int m0  = blockIdx.y * 128;
    if (m0 >= cnt) return;
    int c0  = blockIdx.x * 128;

    __shared__ float As[2][16][128];
    __shared__ float Bs[2][16][128];

    int tid  = threadIdx.x;
    int tx   = tid & 15, ty = tid >> 4;
    int lrow = tid >> 1;
    int lcol = (tid & 1) * 8;

    int rA = m0 + lrow; if (rA > cnt - 1) rA = cnt - 1;
    const float* pA = g_A2 + (size_t)(off + rA) * KT2 + lcol;
    int colB = c0 + lrow;
    const float* pBmain = w2 + ((size_t)e * H_ + colB) * I_ + lcol;

    float acc[8][8];
    #pragma unroll
    for (int i = 0; i < 8; i++)
        #pragma unroll
        for (int j = 0; j < 8; j++) acc[i][j] = 0.f;

    float4 va0, va1, vb0, vb1;
    { const float4* a = (const float4*)pA;     va0 = a[0]; va1 = a[1];
      const float4* b = (const float4*)pBmain; vb0 = b[0]; vb1 = b[1]; }

    for (int kt = 0; kt < NKT2; kt++) {
        int buf = kt & 1;
        {   float av[8] = {va0.x,va0.y,va0.z,va0.w,va1.x,va1.y,va1.z,va1.w};
            float bv[8] = {vb0.x,vb0.y,vb0.z,vb0.w,vb1.x,vb1.y,vb1.z,vb1.w};
            #pragma unroll
            for (int u = 0; u < 8; u++) {
                As[buf][lcol+u][lrow] = av[u];
                Bs[buf][lcol+u][lrow] = bv[u];
            }
        }
        __syncthreads();
        if (kt + 1 < NKT2) {
            int k2 = kt + 1;
            const float4* a = (const float4*)(pA + (size_t)k2 * 16);
            va0 = a[0]; va1 = a[1];
            const float* pb;
            if (k2 < I_/16) pb = pBmain + (size_t)k2 * 16;
            else pb = d_b + (((size_t)(k2 - I_/16) * E_ + e) * H_ + colB) * R_ + lcol;
            const float4* b = (const float4*)pb;
            vb0 = b[0]; vb1 = b[1];
        }
        #pragma unroll
        for (int k = 0; k < 16; k++) {
            float4 a0 = *(const float4*)&As[buf][k][ty*4];
            float4 a1 = *(const float4*)&As[buf][k][64 + ty*4];
            float4 b0 = *(const float4*)&Bs[buf][k][tx*4];
            float4 b1 = *(const float4*)&Bs[buf][k][64 + tx*4];
            float av[8] = {a0.x,a0.y,a0.z,a0.w,a1.x,a1.y,a1.z,a1.w};
            float bv[8] = {b0.x,b0.y,b0.z,b0.w,b1.x,b1.y,b1.z,b1.w};
            #pragma unroll
            for (int i = 0; i < 8; i++)
                #pragma unroll
                for (int j = 0; j < 8; j++)
                    acc[i][j] += av[i] * bv[j];
        }
        __syncthreads();
    }

    #pragma unroll
    for (int i = 0; i < 8; i++) {
        int m = (i < 4) ? (ty*4 + i) : (64 + ty*4 + i - 4);
        if (m0 + m >= cnt) continue;
        size_t s = (size_t)(off + m0 + m);
        float4 o0, o1;
        o0.x = acc[i][0]; o0.y = acc[i][1]; o0.z = acc[i][2]; o0.w = acc[i][3];
        o1.x = acc[i][4]; o1.y = acc[i][5]; o1.z = acc[i][6]; o1.w = acc[i][7];
        *(float4*)(g_D + s * (size_t)H_ + c0 + tx*4)      = o0;
        *(float4*)(g_D + s * (size_t)H_ + c0 + 64 + tx*4) = o1;
    }
}

// ============================================================
// 6) combine: out[t] = w0 * D[pos(t,0)] + w1 * D[pos(t,1)]  (deterministic)
// ============================================================
__global__ __launch_bounds__(256) void k_combine(
    const float* __restrict__ tw, float* __restrict__ out) {
    int idx = blockIdx.x * 256 + threadIdx.x;   // T_*H_/4 = 2097152 float4
    int t   = idx >> 9;                         // H_/4 = 512 float4 per row
    int h4  = idx & 511;
    float w0 = tw[2*t], w1 = tw[2*t+1];
    const float4* d0 = (const float4*)(g_D + (size_t)g_pos[2*t]   * H_);
    const float4* d1 = (const float4*)(g_D + (size_t)g_pos[2*t+1] * H_);
    float4 a = d0[h4], b = d1[h4], o;
    o.x = w0*a.x + w1*b.x;
    o.y = w0*a.y + w1*b.y;
    o.z = w0*a.z + w1*b.z;
    o.w = w0*a.w + w1*b.w;
    ((float4*)out)[idx] = o;
}

// ============================================================
extern "C" void kernel_launch(void* const* d_in, const int* in_sizes, int n_in,
                              void* d_out, int out_size) {
    const float* x    = (const float*)d_in[0];
    const float* tw   = (const float*)d_in[1];
    const float* w13  = (const float*)d_in[2];
    const float* w2   = (const float*)d_in[3];
    const float* gu_a = (const float*)d_in[4];
    const float* gu_b = (const float*)d_in[5];
    const float* da   = (const float*)d_in[6];
    const float* db   = (const float*)d_in[7];
    const int*   ids  = (const int*)d_in[8];
    const int*   lidx = (const int*)d_in[9];
    float* out = (float*)d_out;

    k_route  <<<1, 256>>>(ids);
    k_prep1  <<<P_, 256>>>(x, gu_a, ids, lidx);
    k_gemm1  <<<dim3(I_/64,  P_/128, E_), 256>>>(w13, gu_b);
    k_prep2  <<<P_, 256>>>(da, ids, lidx);
    k_gemm2  <<<dim3(H_/128, P_/128, E_), 256>>>(w2, db);
    k_combine<<<(T_*H_/4)/256, 256>>>(tw, out);
}

// round 3
// speedup vs baseline: 2.1359x; 2.1359x over previous
#include <cuda_runtime.h>
#include <cuda_bf16.h>
#include <math.h>
#include <stdint.h>

#define E_  8
#define H_  2048
#define I_  1024
#define I2_ 2048
#define L_  4
#define R_  16
#define T_  4096
#define P_  8192

#define KT1 2112     // H + L*R
#define KT2 1088     // I + L*R

// -------- scratch (device globals; allocation-free) --------
__device__ __nv_bfloat16 g_A1h[(size_t)P_*KT1], g_A1l[(size_t)P_*KT1];
__device__ __nv_bfloat16 g_B1h[(size_t)E_*I2_*KT1], g_B1l[(size_t)E_*I2_*KT1];
__device__ __nv_bfloat16 g_A2h[(size_t)P_*KT2], g_A2l[(size_t)P_*KT2];
__device__ __nv_bfloat16 g_B2h[(size_t)E_*H_*KT2], g_B2l[(size_t)E_*H_*KT2];
__device__ float g_D[(size_t)P_*H_];
__device__ int   g_list[P_], g_pos[P_], g_off[E_+1];

// -------- helpers --------
__device__ __forceinline__ uint32_t smem_u32(const void* p) {
    uint32_t a;
    asm("{ .reg .u64 t; cvta.to.shared.u64 t, %1; cvt.u32.u64 %0, t; }" : "=r"(a) : "l"(p));
    return a;
}
__device__ __forceinline__ uint32_t pk2(__nv_bfloat16 a, __nv_bfloat16 b) {
    __nv_bfloat162 t = __halves2bfloat162(a, b);
    return *reinterpret_cast<uint32_t*>(&t);
}
__device__ __forceinline__ void split2(float v, __nv_bfloat16& h, __nv_bfloat16& l) {
    h = __float2bfloat16(v);
    l = __float2bfloat16(v - __bfloat162float(h));
}
__device__ __forceinline__ void cp16(uint32_t dst, const void* src) {
    asm volatile("cp.async.cg.shared.global [%0], [%1], 16;" :: "r"(dst), "l"(src));
}
#define CP_COMMIT() asm volatile("cp.async.commit_group;" ::: "memory")
#define CP_WAIT2()  asm volatile("cp.async.wait_group 2;" ::: "memory")
#define CP_WAIT0()  asm volatile("cp.async.wait_group 0;" ::: "memory")

__device__ __forceinline__ void ldsm4(uint32_t* r, uint32_t addr) {
    asm volatile("ldmatrix.sync.aligned.m8n8.x4.shared.b16 {%0,%1,%2,%3}, [%4];"
        : "=r"(r[0]), "=r"(r[1]), "=r"(r[2]), "=r"(r[3]) : "r"(addr));
}
__device__ __forceinline__ void mma_bf16(float* d, const uint32_t* a, const uint32_t* b) {
    asm volatile(
        "mma.sync.aligned.m16n8k16.row.col.f32.bf16.bf16.f32 "
        "{%0,%1,%2,%3}, {%4,%5,%6,%7}, {%8,%9}, {%0,%1,%2,%3};"
        : "+f"(d[0]), "+f"(d[1]), "+f"(d[2]), "+f"(d[3])
        : "r"(a[0]), "r"(a[1]), "r"(a[2]), "r"(a[3]), "r"(b[0]), "r"(b[1]));
}
// swizzled smem offset for a [128 rows x 32 bf16] tile; r=row, c=16B chunk (0..3)
__device__ __forceinline__ uint32_t swz(int r, int c) {
    return (uint32_t)(r * 64 + ((c ^ ((r >> 1) & 3)) << 4));
}

// ============================================================
// routing
// ============================================================
__global__ void k_route(const int* __restrict__ topk_ids) {
    __shared__ int cnt[E_], cur[E_];
    int tid = threadIdx.x;
    if (tid < E_) cnt[tid] = 0;
    __syncthreads();
    for (int p = tid; p < P_; p += blockDim.x) atomicAdd(&cnt[topk_ids[p]], 1);
    __syncthreads();
    if (tid == 0) {
        int acc = 0;
        for (int e = 0; e < E_; e++) { g_off[e] = acc; cur[e] = acc; acc += cnt[e]; }
        g_off[E_] = acc;
    }
    __syncthreads();
    for (int p = tid; p < P_; p += blockDim.x) {
        int e = topk_ids[p];
        int pos = atomicAdd(&cur[e], 1);
        g_list[pos] = p;
        g_pos[p]    = pos;
    }
}

// ============================================================
// prep1: A1 rows (bf16 hi/lo): [ split(x[t]) | masked split(U) ]
// ============================================================
__global__ __launch_bounds__(256) void k_prep1(
    const float* __restrict__ x, const float* __restrict__ gu_a,
    const int* __restrict__ topk_ids, const int* __restrict__ lora_idx) {
    int s = blockIdx.x, tid = threadIdx.x;
    int p = g_list[s], t = p >> 1;
    int e = topk_ids[p], l = lora_idx[t];
    const float4* x4 = (const float4*)(x + (size_t)t * H_);
    __nv_bfloat16* rh = g_A1h + (size_t)s * KT1;
    __nv_bfloat16* rl = g_A1l + (size_t)s * KT1;

    {
        float4 v0 = x4[tid*2], v1 = x4[tid*2+1];
        float vv[8] = {v0.x,v0.y,v0.z,v0.w,v1.x,v1.y,v1.z,v1.w};
        __nv_bfloat16 hh[8], ll[8];
        #pragma unroll
        for (int j = 0; j < 8; j++) split2(vv[j], hh[j], ll[j]);
        *(uint4*)(rh + tid*8) = make_uint4(pk2(hh[0],hh[1]),pk2(hh[2],hh[3]),pk2(hh[4],hh[5]),pk2(hh[6],hh[7]));
        *(uint4*)(rl + tid*8) = make_uint4(pk2(ll[0],ll[1]),pk2(ll[2],ll[3]),pk2(ll[4],ll[5]),pk2(ll[6],ll[7]));
    }
    __nv_bfloat16 z = __float2bfloat16(0.f);
    if (tid < L_*R_) { rh[H_+tid] = z; rl[H_+tid] = z; }
    __syncthreads();

    int lane = tid & 31, w = tid >> 5;
    const float4* a4 = (const float4*)(gu_a + (((size_t)l*E_ + e)*R_ + w) * H_);
    const float4* b4 = a4 + (size_t)8 * (H_/4);
    float sa = 0.f, sb = 0.f;
    for (int it = lane; it < H_/4; it += 32) {
        float4 xv = x4[it], av = a4[it], bv = b4[it];
        sa += xv.x*av.x + xv.y*av.y + xv.z*av.z + xv.w*av.w;
        sb += xv.x*bv.x + xv.y*bv.y + xv.z*bv.z + xv.w*bv.w;
    }
    #pragma unroll
    for (int o = 16; o; o >>= 1) {
        sa += __shfl_down_sync(0xffffffffu, sa, o);
        sb += __shfl_down_sync(0xffffffffu, sb, o);
    }
    if (lane == 0) {
        __nv_bfloat16 h, lo2;
        split2(sa, h, lo2); rh[H_+l*R_+w]   = h; rl[H_+l*R_+w]   = lo2;
        split2(sb, h, lo2); rh[H_+l*R_+w+8] = h; rl[H_+l*R_+w+8] = lo2;
    }
}

// ============================================================
// weight conversion
// ============================================================
__global__ __launch_bounds__(256) void k_convw1(
    const float* __restrict__ w13, const float* __restrict__ gu_b) {
    int rc = blockIdx.x, tid = threadIdx.x;
    int e = rc >> 11, c = rc & 2047;
    const float4* src = (const float4*)(w13 + (size_t)rc * H_);
    __nv_bfloat16* bh = g_B1h + (size_t)rc * KT1;
    __nv_bfloat16* bl = g_B1l + (size_t)rc * KT1;
    float4 v0 = src[tid*2], v1 = src[tid*2+1];
    float vv[8] = {v0.x,v0.y,v0.z,v0.w,v1.x,v1.y,v1.z,v1.w};
    __nv_bfloat16 hh[8], ll[8];
    #pragma unroll
    for (int j = 0; j < 8; j++) split2(vv[j], hh[j], ll[j]);
    *(uint4*)(bh + tid*8) = make_uint4(pk2(hh[0],hh[1]),pk2(hh[2],hh[3]),pk2(hh[4],hh[5]),pk2(hh[6],hh[7]));
    *(uint4*)(bl + tid*8) = make_uint4(pk2(ll[0],ll[1]),pk2(ll[2],ll[3]),pk2(ll[4],ll[5]),pk2(ll[6],ll[7]));
    if (tid < L_*R_) {
        int l = tid >> 4, r = tid & 15;
        float v = gu_b[(((size_t)l*E_ + e)*I2_ + c)*R_ + r];
        __nv_bfloat16 h, lo2; split2(v, h, lo2);
        bh[H_+tid] = h; bl[H_+tid] = lo2;
    }
}

__global__ __launch_bounds__(256) void k_convw2(
    const float* __restrict__ w2, const float* __restrict__ d_b) {
    int rc = blockIdx.x, tid = threadIdx.x;
    int e = rc >> 11, c = rc & 2047;
    const float4* src = (const float4*)(w2 + (size_t)rc * I_);
    __nv_bfloat16* bh = g_B2h + (size_t)rc * KT2;
    __nv_bfloat16* bl = g_B2l + (size_t)rc * KT2;
    float4 v0 = src[tid];
    float vv[4] = {v0.x,v0.y,v0.z,v0.w};
    __nv_bfloat16 hh[4], ll[4];
    #pragma unroll
    for (int j = 0; j < 4; j++) split2(vv[j], hh[j], ll[j]);
    *(uint2*)(bh + tid*4) = make_uint2(pk2(hh[0],hh[1]),pk2(hh[2],hh[3]));
    *(uint2*)(bl + tid*4) = make_uint2(pk2(ll[0],ll[1]),pk2(ll[2],ll[3]));
    if (tid < L_*R_) {
        int l = tid >> 4, r = tid & 15;
        float v = d_b[(((size_t)l*E_ + e)*H_ + c)*R_ + r];
        __nv_bfloat16 h, lo2; split2(v, h, lo2);
        bh[I_+tid] = h; bl[I_+tid] = lo2;
    }
}

// ============================================================
// prep2: V = act . d_a  ->  A2 ext (split)
// ============================================================
__global__ __launch_bounds__(256) void k_prep2(
    const float* __restrict__ d_a,
    const int* __restrict__ topk_ids, const int* __restrict__ lora_idx) {
    int s = blockIdx.x, tid = threadIdx.x;
    int p = g_list[s], t = p >> 1;
    int e = topk_ids[p], l = lora_idx[t];
    __nv_bfloat16* rh = g_A2h + (size_t)s * KT2;
    __nv_bfloat16* rl = g_A2l + (size_t)s * KT2;
    __nv_bfloat16 z = __float2bfloat16(0.f);
    if (tid < L_*R_) { rh[I_+tid] = z; rl[I_+tid] = z; }
    __syncthreads();

    int lane = tid & 31, w = tid >> 5;
    const float2* a2 = (const float2*)(d_a + (((size_t)l*E_ + e)*R_ + w) * I_);
    const float2* b2 = a2 + (size_t)8 * (I_/2);
    const __nv_bfloat162* h2 = (const __nv_bfloat162*)rh;
    const __nv_bfloat162* l2 = (const __nv_bfloat162*)rl;
    float sa = 0.f, sb = 0.f;
    for (int it = lane; it < I_/2; it += 32) {
        float2 fh = __bfloat1622float2(h2[it]);
        float2 fl = __bfloat1622float2(l2[it]);
        float a0 = fh.x + fl.x, a1 = fh.y + fl.y;
        float2 av = a2[it], bv = b2[it];
        sa += a0*av.x + a1*av.y;
        sb += a0*bv.x + a1*bv.y;
    }
    #pragma unroll
    for (int o = 16; o; o >>= 1) {
        sa += __shfl_down_sync(0xffffffffu, sa, o);
        sb += __shfl_down_sync(0xffffffffu, sb, o);
    }
    if (lane == 0) {
        __nv_bfloat16 h, lo2;
        split2(sa, h, lo2); rh[I_+l*R_+w]   = h; rl[I_+l*R_+w]   = lo2;
        split2(sb, h, lo2); rh[I_+l*R_+w+8] = h; rl[I_+l*R_+w+8] = lo2;
    }
}

// ============================================================
// mma.sync GEMM: CTA 128x128, K chunks of 32, 4-stage cp.async.
// 3-product bf16 split: hh + hl + lh.
// GEMM==1: cols = 64 gate + 64 up; SwiGLU epilogue -> g_A2 (split bf16)
// GEMM==2: cols = 128 of H;        epilogue -> g_D fp32
// ============================================================
#define STAGE 32768
#define SMEMB (4*STAGE)   // 131072

template<int GEMM>
__global__ __launch_bounds__(256, 1) void k_gemm_mma() {
    constexpr int KTOT = (GEMM == 1) ? KT1 : KT2;
    constexpr int NK   = KTOT / 32;
    const __nv_bfloat16* Ah = (GEMM == 1) ? g_A1h : g_A2h;
    const __nv_bfloat16* Al = (GEMM == 1) ? g_A1l : g_A2l;
    const __nv_bfloat16* Bh = (GEMM == 1) ? g_B1h : g_B2h;
    const __nv_bfloat16* Bl = (GEMM == 1) ? g_B1l : g_B2l;

    int e   = blockIdx.z;
    int off = g_off[e];
    int cnt = g_off[e+1] - off;
    int m0  = blockIdx.y * 128;
    if (m0 >= cnt) return;

    extern __shared__ char smem_raw[];
    uint32_t sbase = smem_u32(smem_raw);

    int tid = threadIdx.x;
    int lane = tid & 31, wid = tid >> 5;
    int wm = wid >> 2, wn = wid & 3;

    // ---- loader setup: ids {tid, tid+256}; r = id>>2, c = id&3 ----
    const __nv_bfloat16* gaddrA[2][2];  // [idslot][split]
    const __nv_bfloat16* gaddrB[2][2];
    uint32_t sA[2], sB[2];
    #pragma unroll
    for (int j = 0; j < 2; j++) {
        int id = tid + 256*j;
        int r = id >> 2, c = id & 3;
        int rA = m0 + r; if (rA > cnt-1) rA = cnt-1;
        size_t ao = (size_t)(off + rA) * KTOT + c*8;
        gaddrA[j][0] = Ah + ao;  gaddrA[j][1] = Al + ao;
        int colB;
        if (GEMM == 1) colB = (r < 64) ? (blockIdx.x*64 + r) : (I_ + blockIdx.x*64 + r - 64);
        else           colB = blockIdx.x*128 + r;
        size_t bo = ((size_t)e * 2048 + colB) * KTOT + c*8;
        gaddrB[j][0] = Bh + bo;  gaddrB[j][1] = Bl + bo;
        sA[j] = swz(r, c);
        sB[j] = swz(r, c);
    }

    auto issue = [&](int kt) {
        uint32_t st = sbase + (kt & 3) * STAGE;
        size_t kadd = (size_t)kt * 32;
        #pragma unroll
        for (int j = 0; j < 2; j++) {
            cp16(st +         sA[j], gaddrA[j][0] + kadd);
            cp16(st +  8192 + sA[j], gaddrA[j][1] + kadd);
            cp16(st + 16384 + sB[j], gaddrB[j][0] + kadd);
            cp16(st + 24576 + sB[j], gaddrB[j][1] + kadd);
        }
    };

    // ---- ldmatrix lane geometry ----
    int aRow[4], bRow[2];
    #pragma unroll
    for (int i = 0; i < 4; i++) aRow[i] = wm*64 + i*16 + (lane & 15);
    int aC = (lane >> 4) & 1;
    #pragma unroll
    for (int g = 0; g < 2; g++) bRow[g] = wn*32 + g*16 + (lane & 7) + ((lane & 16) ? 8 : 0);
    int bC = (lane >> 3) & 1;

    float acc[4][4][4];
    #pragma unroll
    for (int i = 0; i < 4; i++)
        #pragma unroll
        for (int j = 0; j < 4; j++)
            #pragma unroll
            for (int q = 0; q < 4; q++) acc[i][j][q] = 0.f;

    // prologue
    issue(0); CP_COMMIT();
    issue(1); CP_COMMIT();
    issue(2); CP_COMMIT();

    for (int kt = 0; kt < NK; kt++) {
        CP_WAIT2();
        __syncthreads();
        if (kt + 3 < NK) issue(kt + 3);
        CP_COMMIT();

        uint32_t st = sbase + (kt & 3) * STAGE;
        #pragma unroll
        for (int h = 0; h < 2; h++) {
            uint32_t ah[4][4], al[4][4], bh[2][4], bl[2][4];
            #pragma unroll
            for (int i = 0; i < 4; i++) {
                uint32_t o = swz(aRow[i], 2*h + aC);
                ldsm4(ah[i], st + o);
                ldsm4(al[i], st + 8192 + o);
            }
            #pragma unroll
            for (int g = 0; g < 2; g++) {
                uint32_t o = swz(bRow[g], 2*h + bC);
                ldsm4(bh[g], st + 16384 + o);
                ldsm4(bl[g], st + 24576 + o);
            }
            #pragma unroll
            for (int i = 0; i < 4; i++)
                #pragma unroll
                for (int j = 0; j < 4; j++) {
                    const uint32_t* Bhj = &bh[j>>1][(j&1)*2];
                    const uint32_t* Blj = &bl[j>>1][(j&1)*2];
                    mma_bf16(acc[i][j], ah[i], Bhj);
                    mma_bf16(acc[i][j], ah[i], Blj);
                    mma_bf16(acc[i][j], al[i], Bhj);
                }
        }
    }
    CP_WAIT0();
    __syncthreads();

    if constexpr (GEMM == 1) {
        float* ex = reinterpret_cast<float*>(smem_raw);   // [128][132]
        #pragma unroll
        for (int i = 0; i < 4; i++)
            #pragma unroll
            for (int j = 0; j < 4; j++) {
                int r0 = wm*64 + i*16 + (lane >> 2);
                int c  = wn*32 + j*8 + (lane & 3)*2;
                ex[r0*132 + c]       = acc[i][j][0];
                ex[r0*132 + c + 1]   = acc[i][j][1];
                ex[(r0+8)*132 + c]   = acc[i][j][2];
                ex[(r0+8)*132 + c+1] = acc[i][j][3];
            }
        __syncthreads();
        int m = tid >> 1, half = tid & 1;
        if (m0 + m < cnt) {
            size_t srow = (size_t)(off + m0 + m);
            __nv_bfloat16* dh = g_A2h + srow * KT2 + blockIdx.x*64 + half*32;
            __nv_bfloat16* dl = g_A2l + srow * KT2 + blockIdx.x*64 + half*32;
            const float* gr = ex + m*132 + half*32;
            #pragma unroll
            for (int q = 0; q < 4; q++) {
                uint32_t hw[4], lw[4];
                #pragma unroll
                for (int u = 0; u < 4; u++) {
                    float g0 = gr[q*8 + u*2], g1 = gr[q*8 + u*2 + 1];
                    float u0 = gr[64 + q*8 + u*2], u1 = gr[64 + q*8 + u*2 + 1];
                    float a0 = u0 * g0 / (1.f + expf(-g0));
                    float a1 = u1 * g1 / (1.f + expf(-g1));
                    __nv_bfloat16 h0, l0, h1, l1;
                    split2(a0, h0, l0); split2(a1, h1, l1);
                    hw[u] = pk2(h0, h1); lw[u] = pk2(l0, l1);
                }
                *(uint4*)(dh + q*8) = make_uint4(hw[0], hw[1], hw[2], hw[3]);
                *(uint4*)(dl + q*8) = make_uint4(lw[0], lw[1], lw[2], lw[3]);
            }
        }
    } else {
        int c0 = blockIdx.x * 128;
        #pragma unroll
        for (int i = 0; i < 4; i++) {
            int r0 = m0 + wm*64 + i*16 + (lane >> 2);
            #pragma unroll
            for (int j = 0; j < 4; j++) {
                int c = c0 + wn*32 + j*8 + (lane & 3)*2;
                if (r0 < cnt)
                    *(float2*)(g_D + (size_t)(off + r0) * H_ + c) =
                        make_float2(acc[i][j][0], acc[i][j][1]);
                if (r0 + 8 < cnt)
                    *(float2*)(g_D + (size_t)(off + r0 + 8) * H_ + c) =
                        make_float2(acc[i][j][2], acc[i][j][3]);
            }
        }
    }
}

// ============================================================
// combine
// ============================================================
__global__ __launch_bounds__(256) void k_combine(
    const float* __restrict__ tw, float* __restrict__ out) {
    int idx = blockIdx.x * 256 + threadIdx.x;
    int t = idx >> 9, h4 = idx & 511;
    float w0 = tw[2*t], w1 = tw[2*t+1];
    const float4* d0 = (const float4*)(g_D + (size_t)g_pos[2*t]   * H_);
    const float4* d1 = (const float4*)(g_D + (size_t)g_pos[2*t+1] * H_);
    float4 a = d0[h4], b = d1[h4], o;
    o.x = w0*a.x + w1*b.x; o.y = w0*a.y + w1*b.y;
    o.z = w0*a.z + w1*b.z; o.w = w0*a.w + w1*b.w;
    ((float4*)out)[idx] = o;
}

// ============================================================
extern "C" void kernel_launch(void* const* d_in, const int* in_sizes, int n_in,
                              void* d_out, int out_size) {
    const float* x    = (const float*)d_in[0];
    const float* tw   = (const float*)d_in[1];
    const float* w13  = (const float*)d_in[2];
    const float* w2   = (const float*)d_in[3];
    const float* gu_a = (const float*)d_in[4];
    const float* gu_b = (const float*)d_in[5];
    const float* da   = (const float*)d_in[6];
    const float* db   = (const float*)d_in[7];
    const int*   ids  = (const int*)d_in[8];
    const int*   lidx = (const int*)d_in[9];
    float* out = (float*)d_out;

    cudaFuncSetAttribute(k_gemm_mma<1>, cudaFuncAttributeMaxDynamicSharedMemorySize, SMEMB);
    cudaFuncSetAttribute(k_gemm_mma<2>, cudaFuncAttributeMaxDynamicSharedMemorySize, SMEMB);

    k_route  <<<1, 256>>>(ids);
    k_convw1 <<<E_*I2_, 256>>>(w13, gu_b);
    k_convw2 <<<E_*H_,  256>>>(w2, db);
    k_prep1  <<<P_, 256>>>(x, gu_a, ids, lidx);
    k_gemm_mma<1><<<dim3(16, 64, E_), 256, SMEMB>>>();
    k_prep2  <<<P_, 256>>>(da, ids, lidx);
    k_gemm_mma<2><<<dim3(16, 64, E_), 256, SMEMB>>>();
    k_combine<<<(T_*H_/4)/256, 256>>>(tw, out);
}